// round 6
// baseline (speedup 1.0000x reference)
#include <cuda_runtime.h>
#include <cstddef>

#define TT 4096
#define KK 16
#define BB 32
#define LCH 32
#define NPOS (TT / LCH)            // 128 positions per batch
#define NCHUNK (BB * NPOS)         // 4096 chunks
#define NWARP (NCHUNK / 2)         // 2048 paired warps
#define RHO_C 0.001f
#define NEG_INF_C (-1000000.0f)
#define FLOORP 1e-10f

__device__ float g_S[NCHUNK * 256];   // per-chunk 16x16 transfer matrix [chunk][col][row]
__device__ float g_v0[NCHUNK * 16];   // (unnormalized) alpha entering each chunk

// ---------------------------------------------------------------------------
// Phase 1: per-chunk transfer matrices + fused A-tensor writes.
// One warp = two chunks: lanes 0-15 -> (b, p), lanes 16-31 -> (b+16, p).
// Same position p keeps trip counts warp-uniform; width-16 shuffles converged.
// ---------------------------------------------------------------------------
__global__ void __launch_bounds__(32) phase1_kernel(const float* __restrict__ em,
                                                    const float* __restrict__ bp,
                                                    float4* __restrict__ A4) {
    __shared__ float s_E[2][LCH * KK];
    __shared__ float s_cf[2][LCH * 8];
    const unsigned FULL = 0xffffffffu;
    int lane = threadIdx.x;
    int hw = lane >> 4, hl = lane & 15;
    int k = blockIdx.x;
    int b = (k >> 7) + hw * 16;
    int p = k & 127;
    size_t base_t = (size_t)b * TT + (size_t)p * LCH;

    // stage exp(emissions) for this half's chunk
    const float4* src = (const float4*)(em + base_t * KK);
    float4* dstE = (float4*)s_E[hw];
    for (int i = hl; i < LCH * KK / 4; i += 16) {
        float4 v = src[i];
        dstE[i] = make_float4(__expf(v.x), __expf(v.y), __expf(v.z), __expf(v.w));
    }
    // stage folded coefficients + write this step's 16x16 A block (fused)
    for (int i = hl; i < LCH; i += 16) {
        float bpt = bp[base_t + i];
        float eta = fminf(fmaxf(0.02f + 0.33f * bpt, 0.001f), 0.95f);
        float stay = fmaxf((1.0f - eta) - RHO_C, 0.01f);
        float r0 = (1.0f - eta) + eta;
        float rm = (RHO_C + stay) + eta;
        float rl = RHO_C + (1.0f - RHO_C);
        float ir0 = __fdividef(1.0f, r0), irm = __fdividef(1.0f, rm), irl = __fdividef(1.0f, rl);
        float4* cf = (float4*)&s_cf[hw][i * 8];
        cf[0] = make_float4(eta * ir0 - FLOORP, eta * irm - FLOORP,
                            (1.0f - eta) * ir0 - FLOORP, stay * irm - FLOORP);
        cf[1] = make_float4((1.0f - RHO_C) * irl - FLOORP, RHO_C * irm - FLOORP,
                            RHO_C * irl - FLOORP, 0.0f);

        float4* Arow = A4 + (base_t + i) * 64;
#pragma unroll
        for (int r = 0; r < 16; r++) {
            float iri = (r == 0) ? ir0 : ((r == 15) ? irl : irm);
            float dgv = ((r == 0) ? (1.0f - eta) : ((r == 15) ? (1.0f - RHO_C) : stay)) * iri;
            float ev = eta * iri;
            float rv = RHO_C * iri;
#pragma unroll
            for (int cg = 0; cg < 4; cg++) {
                float x[4];
#pragma unroll
                for (int q = 0; q < 4; q++) {
                    int j = cg * 4 + q;
                    x[q] = (j == r) ? dgv : ((j == r + 1) ? ev : ((j == r - 1) ? rv : 0.0f));
                }
                Arow[r * 4 + cg] = make_float4(x[0], x[1], x[2], x[3]);
            }
        }
    }
    __syncwarp();

    float w[16];
#pragma unroll
    for (int r = 0; r < 16; r++) w[r] = (r == hl) ? 1.0f : 0.0f;
    float csum = 1.0f;

    int t0 = (p == 0) ? 1 : 0;           // warp-uniform
    for (int tl = t0; tl < LCH; ++tl) {
        const float4* cf = (const float4*)&s_cf[hw][tl * 8];
        float4 ca = cf[0], cb = cf[1];
        const float* Et = &s_E[hw][tl * KK];
        float y[16];
#pragma unroll
        for (int r = 0; r < 16; r++) {
            float um1 = w[(r + 15) & 15];
            float up1 = w[(r + 1) & 15];
            float ec = (r == 0) ? 0.0f : (r == 1 ? ca.x : ca.y);
            float dc = (r == 0) ? ca.z : (r == 15 ? cb.x : ca.w);
            float rc = (r == 15) ? 0.0f : (r == 14 ? cb.z : cb.y);
            float q = fmaf(dc, w[r], fmaf(rc, up1, ec * um1));
            float P = fmaf(FLOORP, csum, q);
            y[r] = P * Et[r];
        }
        float a0 = (y[0] + y[4]) + (y[8] + y[12]);
        float a1 = (y[1] + y[5]) + (y[9] + y[13]);
        float a2 = (y[2] + y[6]) + (y[10] + y[14]);
        float a3 = (y[3] + y[7]) + (y[11] + y[15]);
        float cs2 = (a0 + a1) + (a2 + a3);
        float sc = __shfl_sync(FULL, cs2, 0, 16);   // per-half col-0 rescale
        float isc = __fdividef(1.0f, sc);
#pragma unroll
        for (int r = 0; r < 16; r++) w[r] = y[r] * isc;
        csum = cs2 * isc;
    }
    float* out = g_S + (size_t)(b * NPOS + p) * 256 + hl * 16;
#pragma unroll
    for (int r = 0; r < 16; r += 4)
        *(float4*)(out + r) = make_float4(w[r], w[r + 1], w[r + 2], w[r + 3]);
}

// ---------------------------------------------------------------------------
// Phase 2: serial composition per batch — 127 matvecs. Rescale by row-0's
// value (single broadcast): phase3 is scale-invariant w.r.t. its start.
// ---------------------------------------------------------------------------
__global__ void __launch_bounds__(32) phase2_kernel(const float* __restrict__ em,
                                                    const float* __restrict__ mk) {
    int b = blockIdx.x;
    int lane = threadIdx.x;
    int j = lane & 15;
    const unsigned FULL = 0xffffffffu;

    float em0 = __ldg(em + (size_t)b * TT * KK);
    float emj = __ldg(em + (size_t)b * TT * KK + j);
    float m0 = __ldg(mk + (size_t)b * TT);
    float la0 = (j == 0) ? 0.0f : (NEG_INF_C + emj - em0);
    la0 = m0 * la0 + (1.0f - m0) * ((j == 0) ? 0.0f : NEG_INF_C);
    float u = expf(la0);
    if (lane < 16) g_v0[(size_t)(b * NPOS) * 16 + j] = u;

    const float* Sb = g_S + (size_t)b * NPOS * 256;
    float s[16];
#pragma unroll
    for (int c = 0; c < 16; c++) s[c] = Sb[c * 16 + j];

    for (int p = 0; p < NPOS - 1; ++p) {
        float sn[16];
        if (p + 1 < NPOS - 1) {
            const float* Sn = Sb + (size_t)(p + 1) * 256;
#pragma unroll
            for (int c = 0; c < 16; c++) sn[c] = Sn[c * 16 + j];
        }
        // y_j = sum_c S[c][j] * u_c  (4 parallel FMA chains)
        float y0 = 0.f, y1 = 0.f, y2 = 0.f, y3 = 0.f;
#pragma unroll
        for (int c = 0; c < 16; c += 4) {
            y0 = fmaf(s[c + 0], __shfl_sync(FULL, u, c + 0, 16), y0);
            y1 = fmaf(s[c + 1], __shfl_sync(FULL, u, c + 1, 16), y1);
            y2 = fmaf(s[c + 2], __shfl_sync(FULL, u, c + 2, 16), y2);
            y3 = fmaf(s[c + 3], __shfl_sync(FULL, u, c + 3, 16), y3);
        }
        float y = (y0 + y1) + (y2 + y3);
        float ysc = __shfl_sync(FULL, y, 0, 16);    // rescale only (all S entries > 0)
        u = y * __fdividef(1.0f, ysc);
        if (lane < 16) g_v0[(size_t)(b * NPOS + p + 1) * 16 + j] = u;
#pragma unroll
        for (int c = 0; c < 16; c++) s[c] = sn[c];
    }
}

// ---------------------------------------------------------------------------
// Phase 3: re-scan each chunk, emitting all outputs. One warp = two chunks
// (same pairing as phase1). Carry unnormalized w; 1/sum folded per step;
// sum(w) = exp(lZ_{t-1}) -> outputs deferred one iteration. Scale-invariant
// in the start vector, so the unnormalized g_v0 is fine.
// ---------------------------------------------------------------------------
__global__ void __launch_bounds__(32) phase3_kernel(
    const float* __restrict__ em, const float* __restrict__ bp,
    const float* __restrict__ mk,
    float* __restrict__ bel, float* __restrict__ lbel, float* __restrict__ lnr)
{
    __shared__ float s_E[2][LCH * KK];
    __shared__ float s_cf[2][LCH * 8];
    __shared__ float s_mk[2][LCH];
    const unsigned FULL = 0xffffffffu;
    int lane = threadIdx.x;
    int hw = lane >> 4, j = lane & 15;
    int k = blockIdx.x;
    int b = (k >> 7) + hw * 16;
    int p = k & 127;
    size_t base_t = (size_t)b * TT + (size_t)p * LCH;

    const float4* src = (const float4*)(em + base_t * KK);
    float4* dstE = (float4*)s_E[hw];
    for (int i = j; i < LCH * KK / 4; i += 16) {
        float4 v = src[i];
        dstE[i] = make_float4(__expf(v.x), __expf(v.y), __expf(v.z), __expf(v.w));
    }
    for (int i = j; i < LCH; i += 16) {
        float bpt = bp[base_t + i];
        float eta = fminf(fmaxf(0.02f + 0.33f * bpt, 0.001f), 0.95f);
        float stay = fmaxf((1.0f - eta) - RHO_C, 0.01f);
        float r0 = (1.0f - eta) + eta;
        float rm = (RHO_C + stay) + eta;
        float rl = RHO_C + (1.0f - RHO_C);
        float ir0 = __fdividef(1.0f, r0), irm = __fdividef(1.0f, rm), irl = __fdividef(1.0f, rl);
        float4* cf = (float4*)&s_cf[hw][i * 8];
        cf[0] = make_float4(eta * ir0 - FLOORP, eta * irm - FLOORP,
                            (1.0f - eta) * ir0 - FLOORP, stay * irm - FLOORP);
        cf[1] = make_float4((1.0f - RHO_C) * irl - FLOORP, RHO_C * irm - FLOORP,
                            RHO_C * irl - FLOORP, 0.0f);
        s_mk[hw][i] = mk[base_t + i];
    }
    __syncwarp();

    float* belb  = bel  + base_t * KK;
    float* lbelb = lbel + base_t * KK;
    float* lnrb  = lnr  + base_t;

    float w;
    int t0;
    if (p == 0) {                         // warp-uniform
        float em0 = __ldg(em + (size_t)b * TT * KK);
        float emj = __ldg(em + (size_t)b * TT * KK + j);
        float m0 = s_mk[hw][0];
        float la0 = (j == 0) ? 0.0f : (NEG_INF_C + emj - em0);
        la0 = m0 * la0 + (1.0f - m0) * ((j == 0) ? 0.0f : NEG_INF_C);
        w = expf(la0);
        belb[j] = w;
        lbelb[j] = la0;
        if (j == 0) lnrb[0] = m0 * em0;   // lZ0 == em[b,0,0] exactly
        t0 = 1;
    } else {
        w = g_v0[(size_t)(b * NPOS + p) * 16 + j];
        t0 = 0;
    }

    for (int tl = t0; tl < LCH; ++tl) {
        const float4* cf = (const float4*)&s_cf[hw][tl * 8];
        float4 ca = cf[0], cb = cf[1];
        float E = s_E[hw][tl * KK + j];

        float c = w;
#pragma unroll
        for (int s = 8; s >= 1; s >>= 1)
            c += __shfl_xor_sync(FULL, c, s, 16);
        float ic = __fdividef(1.0f, c);

        float um1 = __shfl_sync(FULL, w, (j + 15) & 15, 16);
        float up1 = __shfl_sync(FULL, w, (j + 1) & 15, 16);
        float ec = (j == 0) ? 0.0f : (j == 1 ? ca.x : ca.y);
        float dc = (j == 0) ? ca.z : (j == 15 ? cb.x : ca.w);
        float rc = (j == 15) ? 0.0f : (j == 14 ? cb.z : cb.y);
        float q = fmaf(dc, w, fmaf(rc, up1, ec * um1));
        float wn = fmaf(ic, q, FLOORP) * E;

        if (tl > t0) {                    // deferred outputs for t = base+tl-1
            float lZ = __logf(c);
            belb[(tl - 1) * KK + j]  = w * ic;
            lbelb[(tl - 1) * KK + j] = __logf(w) - lZ;
            if (j == 0) lnrb[tl - 1] = s_mk[hw][tl - 1] * lZ;
        }
        w = wn;
    }
    float c = w;
#pragma unroll
    for (int s = 8; s >= 1; s >>= 1)
        c += __shfl_xor_sync(FULL, c, s, 16);
    float ic = __fdividef(1.0f, c);
    float lZ = __logf(c);
    belb[(LCH - 1) * KK + j]  = w * ic;
    lbelb[(LCH - 1) * KK + j] = __logf(w) - lZ;
    if (j == 0) lnrb[LCH - 1] = s_mk[hw][LCH - 1] * lZ;
}

// ---------------------------------------------------------------------------
extern "C" void kernel_launch(void* const* d_in, const int* in_sizes, int n_in,
                              void* d_out, int out_size) {
    const float* em = (const float*)d_in[0];
    const float* bp = (const float*)d_in[1];
    const float* mk = (const float*)d_in[2];
    float* out = (float*)d_out;

    const size_t BTK = (size_t)BB * TT * KK;
    const size_t BT  = (size_t)BB * TT;
    float* bel  = out;
    float* lbel = out + BTK;
    float* lnr  = out + 2 * BTK;
    float* A    = out + 2 * BTK + BT;

    phase1_kernel<<<NWARP, 32>>>(em, bp, (float4*)A);
    phase2_kernel<<<BB, 32>>>(em, mk);
    phase3_kernel<<<NWARP, 32>>>(em, bp, mk, bel, lbel, lnr);
}

// round 7
// speedup vs baseline: 1.9608x; 1.9608x over previous
#include <cuda_runtime.h>
#include <cstddef>

#define TT 4096
#define KK 16
#define BB 32
#define LCH 32
#define NPOS (TT / LCH)            // 128 positions per batch
#define NCHUNK (BB * NPOS)         // 4096 chunks
#define NWARP (NCHUNK / 2)         // 2048 paired warps
#define RHO_C 0.001f
#define NEG_INF_C (-1000000.0f)
#define FLOORP 1e-10f

__device__ float g_S[NCHUNK * 256];   // per-chunk 16x16 transfer matrix [chunk][col][row]
__device__ float g_v0[NCHUNK * 16];   // (unnormalized) alpha entering each chunk

// ---------------------------------------------------------------------------
// Phase 1: per-chunk transfer matrices + fused, fully-COALESCED A writes.
// One warp = two chunks: lanes 0-15 -> (b, p), lanes 16-31 -> (b+16, p).
// A values are recovered from the staged folded coefficients (cf + FLOORP),
// and each 1KB A-block is written by the whole warp: 2 STG.128 per lane,
// 64 consecutive float4s per step.
// ---------------------------------------------------------------------------
__global__ void __launch_bounds__(32) phase1_kernel(const float* __restrict__ em,
                                                    const float* __restrict__ bp,
                                                    float4* __restrict__ A4) {
    __shared__ float s_E[2][LCH * KK];
    __shared__ float s_cf[2][LCH * 8];
    const unsigned FULL = 0xffffffffu;
    int lane = threadIdx.x;
    int hw = lane >> 4, hl = lane & 15;
    int k = blockIdx.x;
    int b = (k >> 7) + hw * 16;
    int p = k & 127;
    size_t base_t = (size_t)b * TT + (size_t)p * LCH;

    // stage exp(emissions)
    const float4* src = (const float4*)(em + base_t * KK);
    float4* dstE = (float4*)s_E[hw];
    for (int i = hl; i < LCH * KK / 4; i += 16) {
        float4 v = src[i];
        dstE[i] = make_float4(__expf(v.x), __expf(v.y), __expf(v.z), __expf(v.w));
    }
    // stage folded coefficients
    for (int i = hl; i < LCH; i += 16) {
        float bpt = bp[base_t + i];
        float eta = fminf(fmaxf(0.02f + 0.33f * bpt, 0.001f), 0.95f);
        float stay = fmaxf((1.0f - eta) - RHO_C, 0.01f);
        float r0 = (1.0f - eta) + eta;
        float rm = (RHO_C + stay) + eta;
        float rl = RHO_C + (1.0f - RHO_C);
        float ir0 = __fdividef(1.0f, r0), irm = __fdividef(1.0f, rm), irl = __fdividef(1.0f, rl);
        float4* cf = (float4*)&s_cf[hw][i * 8];
        cf[0] = make_float4(eta * ir0 - FLOORP, eta * irm - FLOORP,
                            (1.0f - eta) * ir0 - FLOORP, stay * irm - FLOORP);
        cf[1] = make_float4((1.0f - RHO_C) * irl - FLOORP, RHO_C * irm - FLOORP,
                            RHO_C * irl - FLOORP, 0.0f);
    }
    __syncwarp();

    // ---- COALESCED A writes: whole warp per 16x16 block (64 float4 = 1KB) ----
    // lane -> float4 f = lane and lane+32;  row r = f>>2, cols 4*(f&3)..+3
    {
        int f0 = lane, f1 = lane + 32;
        int r_0 = f0 >> 2, c0_0 = (f0 & 3) * 4;
        int r_1 = f1 >> 2, c0_1 = (f1 & 3) * 4;
#pragma unroll
        for (int half = 0; half < 2; half++) {
            size_t bt0 = ((size_t)((k >> 7) + half * 16) * TT) + (size_t)p * LCH;
            for (int i = 0; i < LCH; i++) {
                const float4* cf = (const float4*)&s_cf[half][i * 8];
                float4 ca = cf[0], cb = cf[1];
                float4* blk = A4 + (bt0 + i) * 64;
#pragma unroll
                for (int rep = 0; rep < 2; rep++) {
                    int r  = rep ? r_1 : r_0;
                    int c0 = rep ? c0_1 : c0_0;
                    // recover A row-r values from folded coefs
                    float dg = ((r == 0) ? ca.z : (r == 15) ? cb.x : ca.w) + FLOORP;
                    float ev = ((r == 0) ? ca.x : ca.y) + FLOORP;          // A[r][r+1]
                    float rv = ((r == 15) ? cb.z : cb.y) + FLOORP;         // A[r][r-1]
                    float x[4];
#pragma unroll
                    for (int q = 0; q < 4; q++) {
                        int j = c0 + q;
                        x[q] = (j == r) ? dg : (j == r + 1) ? ev : (j == r - 1) ? rv : 0.0f;
                    }
                    blk[rep ? f1 : f0] = make_float4(x[0], x[1], x[2], x[3]);
                }
            }
        }
    }

    // ---- transfer matrix: lane owns one column ----
    float w[16];
#pragma unroll
    for (int r = 0; r < 16; r++) w[r] = (r == hl) ? 1.0f : 0.0f;
    float csum = 1.0f;

    int t0 = (p == 0) ? 1 : 0;           // warp-uniform
    for (int tl = t0; tl < LCH; ++tl) {
        const float4* cf = (const float4*)&s_cf[hw][tl * 8];
        float4 ca = cf[0], cb = cf[1];
        const float* Et = &s_E[hw][tl * KK];
        float y[16];
#pragma unroll
        for (int r = 0; r < 16; r++) {
            float um1 = w[(r + 15) & 15];
            float up1 = w[(r + 1) & 15];
            float ec = (r == 0) ? 0.0f : (r == 1 ? ca.x : ca.y);
            float dc = (r == 0) ? ca.z : (r == 15 ? cb.x : ca.w);
            float rc = (r == 15) ? 0.0f : (r == 14 ? cb.z : cb.y);
            float q = fmaf(dc, w[r], fmaf(rc, up1, ec * um1));
            float P = fmaf(FLOORP, csum, q);
            y[r] = P * Et[r];
        }
        float a0 = (y[0] + y[4]) + (y[8] + y[12]);
        float a1 = (y[1] + y[5]) + (y[9] + y[13]);
        float a2 = (y[2] + y[6]) + (y[10] + y[14]);
        float a3 = (y[3] + y[7]) + (y[11] + y[15]);
        float cs2 = (a0 + a1) + (a2 + a3);
        float sc = __shfl_sync(FULL, cs2, 0, 16);   // per-half col-0 rescale
        float isc = __fdividef(1.0f, sc);
#pragma unroll
        for (int r = 0; r < 16; r++) w[r] = y[r] * isc;
        csum = cs2 * isc;
    }
    float* out = g_S + (size_t)(b * NPOS + p) * 256 + hl * 16;
#pragma unroll
    for (int r = 0; r < 16; r += 4)
        *(float4*)(out + r) = make_float4(w[r], w[r + 1], w[r + 2], w[r + 3]);
}

// ---------------------------------------------------------------------------
// Phase 2: serial composition per batch — 127 matvecs. Rescale by lane-0's
// value (single broadcast): phase3 is scale-invariant w.r.t. its start.
// ---------------------------------------------------------------------------
__global__ void __launch_bounds__(32) phase2_kernel(const float* __restrict__ em,
                                                    const float* __restrict__ mk) {
    int b = blockIdx.x;
    int lane = threadIdx.x;
    int j = lane & 15;
    const unsigned FULL = 0xffffffffu;

    float em0 = __ldg(em + (size_t)b * TT * KK);
    float emj = __ldg(em + (size_t)b * TT * KK + j);
    float m0 = __ldg(mk + (size_t)b * TT);
    float la0 = (j == 0) ? 0.0f : (NEG_INF_C + emj - em0);
    la0 = m0 * la0 + (1.0f - m0) * ((j == 0) ? 0.0f : NEG_INF_C);
    float u = expf(la0);
    if (lane < 16) g_v0[(size_t)(b * NPOS) * 16 + j] = u;

    const float* Sb = g_S + (size_t)b * NPOS * 256;
    float s[16];
#pragma unroll
    for (int c = 0; c < 16; c++) s[c] = Sb[c * 16 + j];

    for (int p = 0; p < NPOS - 1; ++p) {
        float sn[16];
        if (p + 1 < NPOS - 1) {
            const float* Sn = Sb + (size_t)(p + 1) * 256;
#pragma unroll
            for (int c = 0; c < 16; c++) sn[c] = Sn[c * 16 + j];
        }
        float y0 = 0.f, y1 = 0.f, y2 = 0.f, y3 = 0.f;
#pragma unroll
        for (int c = 0; c < 16; c += 4) {
            y0 = fmaf(s[c + 0], __shfl_sync(FULL, u, c + 0, 16), y0);
            y1 = fmaf(s[c + 1], __shfl_sync(FULL, u, c + 1, 16), y1);
            y2 = fmaf(s[c + 2], __shfl_sync(FULL, u, c + 2, 16), y2);
            y3 = fmaf(s[c + 3], __shfl_sync(FULL, u, c + 3, 16), y3);
        }
        float y = (y0 + y1) + (y2 + y3);
        float ysc = __shfl_sync(FULL, y, 0, 16);    // rescale only (all entries > 0)
        u = y * __fdividef(1.0f, ysc);
        if (lane < 16) g_v0[(size_t)(b * NPOS + p + 1) * 16 + j] = u;
#pragma unroll
        for (int c = 0; c < 16; c++) s[c] = sn[c];
    }
}

// ---------------------------------------------------------------------------
// Phase 3: re-scan each chunk, emitting all outputs. One warp = two chunks.
// Carry unnormalized w; 1/sum folded per step; sum(w) = exp(lZ_{t-1}) ->
// outputs deferred one iteration. Scale-invariant in the start vector.
// ---------------------------------------------------------------------------
__global__ void __launch_bounds__(32) phase3_kernel(
    const float* __restrict__ em, const float* __restrict__ bp,
    const float* __restrict__ mk,
    float* __restrict__ bel, float* __restrict__ lbel, float* __restrict__ lnr)
{
    __shared__ float s_E[2][LCH * KK];
    __shared__ float s_cf[2][LCH * 8];
    __shared__ float s_mk[2][LCH];
    const unsigned FULL = 0xffffffffu;
    int lane = threadIdx.x;
    int hw = lane >> 4, j = lane & 15;
    int k = blockIdx.x;
    int b = (k >> 7) + hw * 16;
    int p = k & 127;
    size_t base_t = (size_t)b * TT + (size_t)p * LCH;

    const float4* src = (const float4*)(em + base_t * KK);
    float4* dstE = (float4*)s_E[hw];
    for (int i = j; i < LCH * KK / 4; i += 16) {
        float4 v = src[i];
        dstE[i] = make_float4(__expf(v.x), __expf(v.y), __expf(v.z), __expf(v.w));
    }
    for (int i = j; i < LCH; i += 16) {
        float bpt = bp[base_t + i];
        float eta = fminf(fmaxf(0.02f + 0.33f * bpt, 0.001f), 0.95f);
        float stay = fmaxf((1.0f - eta) - RHO_C, 0.01f);
        float r0 = (1.0f - eta) + eta;
        float rm = (RHO_C + stay) + eta;
        float rl = RHO_C + (1.0f - RHO_C);
        float ir0 = __fdividef(1.0f, r0), irm = __fdividef(1.0f, rm), irl = __fdividef(1.0f, rl);
        float4* cf = (float4*)&s_cf[hw][i * 8];
        cf[0] = make_float4(eta * ir0 - FLOORP, eta * irm - FLOORP,
                            (1.0f - eta) * ir0 - FLOORP, stay * irm - FLOORP);
        cf[1] = make_float4((1.0f - RHO_C) * irl - FLOORP, RHO_C * irm - FLOORP,
                            RHO_C * irl - FLOORP, 0.0f);
        s_mk[hw][i] = mk[base_t + i];
    }
    __syncwarp();

    float* belb  = bel  + base_t * KK;
    float* lbelb = lbel + base_t * KK;
    float* lnrb  = lnr  + base_t;

    float w;
    int t0;
    if (p == 0) {                         // warp-uniform
        float em0 = __ldg(em + (size_t)b * TT * KK);
        float emj = __ldg(em + (size_t)b * TT * KK + j);
        float m0 = s_mk[hw][0];
        float la0 = (j == 0) ? 0.0f : (NEG_INF_C + emj - em0);
        la0 = m0 * la0 + (1.0f - m0) * ((j == 0) ? 0.0f : NEG_INF_C);
        w = expf(la0);
        belb[j] = w;
        lbelb[j] = la0;
        if (j == 0) lnrb[0] = m0 * em0;   // lZ0 == em[b,0,0] exactly
        t0 = 1;
    } else {
        w = g_v0[(size_t)(b * NPOS + p) * 16 + j];
        t0 = 0;
    }

    for (int tl = t0; tl < LCH; ++tl) {
        const float4* cf = (const float4*)&s_cf[hw][tl * 8];
        float4 ca = cf[0], cb = cf[1];
        float E = s_E[hw][tl * KK + j];

        float c = w;
#pragma unroll
        for (int s = 8; s >= 1; s >>= 1)
            c += __shfl_xor_sync(FULL, c, s, 16);
        float ic = __fdividef(1.0f, c);

        float um1 = __shfl_sync(FULL, w, (j + 15) & 15, 16);
        float up1 = __shfl_sync(FULL, w, (j + 1) & 15, 16);
        float ec = (j == 0) ? 0.0f : (j == 1 ? ca.x : ca.y);
        float dc = (j == 0) ? ca.z : (j == 15 ? cb.x : ca.w);
        float rc = (j == 15) ? 0.0f : (j == 14 ? cb.z : cb.y);
        float q = fmaf(dc, w, fmaf(rc, up1, ec * um1));
        float wn = fmaf(ic, q, FLOORP) * E;

        if (tl > t0) {                    // deferred outputs for t = base+tl-1
            float lZ = __logf(c);
            belb[(tl - 1) * KK + j]  = w * ic;
            lbelb[(tl - 1) * KK + j] = __logf(w) - lZ;
            if (j == 0) lnrb[tl - 1] = s_mk[hw][tl - 1] * lZ;
        }
        w = wn;
    }
    float c = w;
#pragma unroll
    for (int s = 8; s >= 1; s >>= 1)
        c += __shfl_xor_sync(FULL, c, s, 16);
    float ic = __fdividef(1.0f, c);
    float lZ = __logf(c);
    belb[(LCH - 1) * KK + j]  = w * ic;
    lbelb[(LCH - 1) * KK + j] = __logf(w) - lZ;
    if (j == 0) lnrb[LCH - 1] = s_mk[hw][LCH - 1] * lZ;
}

// ---------------------------------------------------------------------------
extern "C" void kernel_launch(void* const* d_in, const int* in_sizes, int n_in,
                              void* d_out, int out_size) {
    const float* em = (const float*)d_in[0];
    const float* bp = (const float*)d_in[1];
    const float* mk = (const float*)d_in[2];
    float* out = (float*)d_out;

    const size_t BTK = (size_t)BB * TT * KK;
    const size_t BT  = (size_t)BB * TT;
    float* bel  = out;
    float* lbel = out + BTK;
    float* lnr  = out + 2 * BTK;
    float* A    = out + 2 * BTK + BT;

    phase1_kernel<<<NWARP, 32>>>(em, bp, (float4*)A);
    phase2_kernel<<<BB, 32>>>(em, mk);
    phase3_kernel<<<NWARP, 32>>>(em, bp, mk, bel, lbel, lnr);
}